// round 17
// baseline (speedup 1.0000x reference)
#include <cuda_runtime.h>
#include <cuda_bf16.h>
#include <cstdint>

#define BATCH 8
#define NPTS  8192
#define NQ    2048
#define NK    32
#define NF    16
#define TILE_PTS 2048

// Output layout: flattened float32 concat of the 5-tuple
static const size_t QP_OFF  = 0;                                   // 8*2048*3      = 49152
static const size_t GF_OFF  = 49152;                               // 8*2048*32*19  = 9961472
static const size_t IDX_OFF = 49152 + 9961472;                     // 10,010,624
static const size_t GPN_OFF = IDX_OFF + (size_t)BATCH*NQ*NK;       // 10,534,912
static const size_t GP_OFF  = GPN_OFF + (size_t)BATCH*NQ*NK*3;     // 12,107,776

__device__ float g_sx[BATCH * NPTS];
__device__ float g_sy[BATCH * NPTS];
__device__ float g_sz[BATCH * NPTS];
__device__ int   g_progress[BATCH];     // queries published per batch

// ---- packed f32x2 helpers (sm_103a): per-lane IEEE .rn, identical to scalar
typedef unsigned long long u64;
__device__ __forceinline__ u64 pack2(float lo, float hi) {
    u64 r; asm("mov.b64 %0, {%1, %2};" : "=l"(r) : "f"(lo), "f"(hi)); return r;
}
__device__ __forceinline__ void unpack2(u64 v, float& lo, float& hi) {
    asm("mov.b64 {%0, %1}, %2;" : "=f"(lo), "=f"(hi) : "l"(v));
}
__device__ __forceinline__ u64 add2(u64 a, u64 b) {
    u64 r; asm("add.rn.f32x2 %0, %1, %2;" : "=l"(r) : "l"(a), "l"(b)); return r;
}
__device__ __forceinline__ u64 mul2(u64 a, u64 b) {
    u64 r; asm("mul.rn.f32x2 %0, %1, %2;" : "=l"(r) : "l"(a), "l"(b)); return r;
}
__device__ __forceinline__ float fneg_exact(float x) {   // sign-bit flip (ALU)
    return __uint_as_float(__float_as_uint(x) ^ 0x80000000u);
}

// ---------------------------------------------------------------------------
// Kernel 0: AoS -> SoA transpose of points; also resets progress counters.
// ---------------------------------------------------------------------------
__global__ void __launch_bounds__(256)
transpose_kernel(const float* __restrict__ pts)
{
    const int i = blockIdx.x * blockDim.x + threadIdx.x;
    if (i < BATCH) g_progress[i] = 0;
    if (i >= BATCH * NPTS) return;
    g_sx[i] = pts[(size_t)i * 3 + 0];
    g_sy[i] = pts[(size_t)i * 3 + 1];
    g_sz[i] = pts[(size_t)i * 3 + 2];
}

// ---------------------------------------------------------------------------
// MEGA KERNEL: 8 FPS CTAs (bids 0-7) + 1024 ball+gather CTAs (bids 8-1031),
// 512 threads each, 120KB dynamic smem per CTA => 1 CTA/SM (ball warps never
// steal issue from the 8 FPS SMs). Wave 1 = bids 0-147 on distinct SMs, so
// FPS CTAs are always resident => ball spin-waits cannot deadlock.
//
// FPS role: R14 kernel VERBATIM (proven fastest: 512thr x 16pts, packed
// f32x2 exact math, REDUX -> atomicMax -> bar -> owner atomicMin -> bar ->
// LDG-broadcast), plus a progress publish every 8 iterations (t0 only:
// threadfence + store; amortized off the critical path).
//
// Ball role: waits for its 16 queries via g_progress (volatile poll +
// nanosleep), then R14 smem-tiled scan (exact arithmetic, in-order ballot
// collection) + inline gather. qp is read with __ldcg (L2) because it is
// produced DURING this launch — avoids stale L1 lines shared across qblocks.
// ---------------------------------------------------------------------------
__global__ void __launch_bounds__(512)
mega_kernel(const float* __restrict__ pts, const float* __restrict__ feat,
            float* __restrict__ out)
{
    extern __shared__ char dsm[];

    if (blockIdx.x < BATCH) {
        // ================= FPS role (R14 verbatim + progress) =============
        const int b = blockIdx.x;
        const int t = threadIdx.x;
        const float* p = pts + (size_t)b * NPTS * 3;
        float* out_qp = out + QP_OFF;

        __shared__ unsigned s_gmax[2];
        __shared__ int      s_best[2];

        u64 PX[8], PY[8], PZ[8];
        float dist[16];
#pragma unroll
        for (int pr = 0; pr < 8; pr++) {
            int i0 = t * 16 + pr * 2;
            float x0 = p[i0 * 3 + 0], y0 = p[i0 * 3 + 1], z0 = p[i0 * 3 + 2];
            float x1 = p[i0 * 3 + 3], y1 = p[i0 * 3 + 4], z1 = p[i0 * 3 + 5];
            PX[pr] = pack2(x0, x1); PY[pr] = pack2(y0, y1); PZ[pr] = pack2(z0, z1);
            dist[pr * 2] = 1e10f; dist[pr * 2 + 1] = 1e10f;
        }
        float cx = __ldg(p + 0), cy = __ldg(p + 1), cz = __ldg(p + 2);
        if (t == 0) {
            s_gmax[0] = 0u; s_gmax[1] = 0u;
            s_best[0] = 0x7fffffff; s_best[1] = 0x7fffffff;
            float* o = out_qp + (size_t)b * NQ * 3;
            o[0] = cx; o[1] = cy; o[2] = cz;
        }
        __syncthreads();

        for (int it = 1; it < NQ; ++it) {
            const int buf = it & 1;
            const float nx = fneg_exact(cx), ny = fneg_exact(cy), nz = fneg_exact(cz);
            const u64 nx2 = pack2(nx, nx);
            const u64 ny2 = pack2(ny, ny);
            const u64 nz2 = pack2(nz, nz);

            float tmax = 0.0f;
#pragma unroll
            for (int pr = 0; pr < 8; pr++) {
                u64 dx2 = add2(PX[pr], nx2);        // x + (-c) == x - c exactly
                u64 dy2 = add2(PY[pr], ny2);
                u64 dz2 = add2(PZ[pr], nz2);
                u64 d2  = add2(add2(mul2(dx2, dx2), mul2(dy2, dy2)), mul2(dz2, dz2));
                float d0, d1; unpack2(d2, d0, d1);
                float n0 = fminf(dist[pr * 2 + 0], d0);
                float n1 = fminf(dist[pr * 2 + 1], d1);
                dist[pr * 2 + 0] = n0; dist[pr * 2 + 1] = n1;
                tmax = fmaxf(tmax, n0);
                tmax = fmaxf(tmax, n1);
            }

            const unsigned ut = __float_as_uint(tmax);
            const unsigned wm = __reduce_max_sync(0xffffffffu, ut);
            if ((t & 31) == 0) atomicMax(&s_gmax[buf], wm);
            __syncthreads();                        // bar1: gmax final

            const unsigned g = s_gmax[buf];
            if (ut == g) {                          // owner thread(s): rare
                int j = 0;
#pragma unroll
                for (int jj = 15; jj >= 0; jj--)    // downward => first match
                    if (__float_as_uint(dist[jj]) == g) j = jj;
                atomicMin(&s_best[buf], t * 16 + j);
            }
            if (t == 0) { s_gmax[buf ^ 1] = 0u; s_best[buf ^ 1] = 0x7fffffff; }
            __syncthreads();                        // bar2: best final

            const int best = s_best[buf];
            const float* pb = p + (size_t)best * 3; // uniform -> L1 broadcast
            cx = __ldg(pb + 0); cy = __ldg(pb + 1); cz = __ldg(pb + 2);
            if (t == 0) {
                float* o = out_qp + ((size_t)b * NQ + it) * 3;
                o[0] = cx; o[1] = cy; o[2] = cz;
                if ((it & 7) == 7) {                // publish every 8 iters
                    __threadfence();
                    g_progress[b] = it + 1;
                }
            }
        }
    } else {
        // ================= ball + gather role =============================
        const int tid  = threadIdx.x;
        const int warp = tid >> 5;                 // 16 warps = 16 queries
        const int lane = tid & 31;
        const int qblock = blockIdx.x - BATCH;     // 0..1023
        const int gq   = qblock * 16 + warp;       // global query id
        const int b    = qblock >> 7;              // batch (uniform per CTA)
        const float R2 = (float)(0.1 * 0.1);       // 0.00999999977648258f
        const float* sx = g_sx + (size_t)b * NPTS;
        const float* sy = g_sy + (size_t)b * NPTS;
        const float* sz = g_sz + (size_t)b * NPTS;

        float* tx = (float*)dsm;
        float* ty = tx + TILE_PTS;
        float* tz = ty + TILE_PTS;
        int*   wi = (int*)(tz + TILE_PTS);         // [16][NK]

        // wait until our 16 queries exist (FPS publishes monotonically)
        if (tid == 0) {
            const int need = ((qblock & 127) << 4) + 16;
            while (*(volatile int*)&g_progress[b] < need) __nanosleep(200);
            __threadfence();
        }
        __syncthreads();

        const float* qp = out + QP_OFF;
        const float qx = __ldcg(qp + (size_t)gq * 3 + 0);   // L2: fresh
        const float qy = __ldcg(qp + (size_t)gq * 3 + 1);
        const float qz = __ldcg(qp + (size_t)gq * 3 + 2);

        int cnt = 0;
        const unsigned lmask = (1u << lane) - 1u;

        for (int tile = 0; tile < NPTS / TILE_PTS; tile++) {
            const int base = tile * TILE_PTS;
            __syncthreads();                       // previous tile consumed
#pragma unroll
            for (int k = 0; k < TILE_PTS / 512; k++) {
                const int i = k * 512 + tid;
                tx[i] = sx[base + i];
                ty[i] = sy[base + i];
                tz[i] = sz[base + i];
            }
            __syncthreads();                       // tile ready

#pragma unroll 4
            for (int c = 0; c < TILE_PTS / 32; c++) {
                const int i = c * 32 + lane;       // conflict-free LDS
                float dx = qx - tx[i];
                float dy = qy - ty[i];
                float dz = qz - tz[i];
                float d  = __fadd_rn(__fadd_rn(__fmul_rn(dx, dx), __fmul_rn(dy, dy)),
                                     __fmul_rn(dz, dz));
                const bool in = (d <= R2);
                const unsigned m = __ballot_sync(0xffffffffu, in);
                if (m) {
                    const int slot = cnt + __popc(m & lmask);
                    if (in && slot < NK) wi[warp * NK + slot] = base + i;
                    cnt += __popc(m);
                }
            }
        }
        __syncwarp();
        const int cf    = cnt < NK ? cnt : NK;
        const int first = wi[warp * NK];
        const int idx   = (lane < cf) ? wi[warp * NK + lane] : first;

        out[IDX_OFF + (size_t)gq * NK + lane] = (float)idx;

        // ---- inline gather (lane = k); strided stores hidden under FPS ----
        const size_t pb = (size_t)b * NPTS + idx;
        const float px = sx[idx];
        const float py = sy[idx];
        const float pz = sz[idx];
        const float nx = px - qx, ny = py - qy, nz = pz - qz;

        const float4* f4 = (const float4*)(feat + pb * NF);
        const float4 f0 = f4[0], f1 = f4[1], f2 = f4[2], f3 = f4[3];

        float* gf = out + GF_OFF + ((size_t)gq * NK + lane) * 19;
        gf[0]  = nx;   gf[1]  = ny;   gf[2]  = nz;
        gf[3]  = f0.x; gf[4]  = f0.y; gf[5]  = f0.z; gf[6]  = f0.w;
        gf[7]  = f1.x; gf[8]  = f1.y; gf[9]  = f1.z; gf[10] = f1.w;
        gf[11] = f2.x; gf[12] = f2.y; gf[13] = f2.z; gf[14] = f2.w;
        gf[15] = f3.x; gf[16] = f3.y; gf[17] = f3.z; gf[18] = f3.w;

        float* gpn = out + GPN_OFF + ((size_t)gq * NK + lane) * 3;
        gpn[0] = nx; gpn[1] = ny; gpn[2] = nz;

        float* gp = out + GP_OFF + ((size_t)gq * NK + lane) * 3;
        gp[0] = px; gp[1] = py; gp[2] = pz;
    }
}

// ---------------------------------------------------------------------------
extern "C" void kernel_launch(void* const* d_in, const int* in_sizes, int n_in,
                              void* d_out, int out_size)
{
    const float* points   = (const float*)d_in[0];
    const float* features = (const float*)d_in[1];
    if (in_sizes[0] != BATCH * NPTS * 3) {
        const float* tmp = points; points = features; features = tmp;
    }
    float* out = (float*)d_out;

    // 120KB dynamic smem/CTA forces 1 CTA/SM (228KB/SM): FPS SMs isolated.
    // (Attribute set is idempotent, not a stream op / allocation.)
    cudaFuncSetAttribute(mega_kernel,
                         cudaFuncAttributeMaxDynamicSharedMemorySize, 122880);

    transpose_kernel<<<(BATCH * NPTS + 255) / 256, 256>>>(points);
    mega_kernel<<<BATCH + (BATCH * NQ) / 16, 512, 122880>>>(points, features, out);
}